// round 5
// baseline (speedup 1.0000x reference)
#include <cuda_runtime.h>

// Problem constants (from reference setup_inputs)
#define B     8
#define NTOT  4096
#define C     32
#define G     4
#define RAD   4
#define RANK  2
#define K     128         // NTOT / C
#define PPC   12          // points per center: 4 neighbor + 4 sampled + 4 rr
#define P     (C * PPC)   // 384 points per (b,k)
#define IN    1024
#define OUTN  1024
#define NWARP (P / 32)    // 12
#define HSIZE 1024        // smem hash table slots (load factor 384/1024)

__global__ void zero_kernel(float* __restrict__ out, int n) {
    int i = blockIdx.x * blockDim.x + threadIdx.x;
    if (i < n) out[i] = 0.0f;
}

__global__ __launch_bounds__(P) void sparse_layer_kernel(
    const float* __restrict__ x,       // (B, IN)
    const float* __restrict__ means,   // (B, K, C, 2)
    const float* __restrict__ sigmas,  // (B, K, C, 2)
    const float* __restrict__ values,  // (B, K, C)
    const float* __restrict__ su,      // (B, K, C, G, 2)
    const float* __restrict__ ru,      // (B, K, C, RAD, 2)
    float* __restrict__ out)           // (B, OUTN)
{
    __shared__ float s_mean[C * 2];
    __shared__ float s_inv[C * 2];
    __shared__ float s_val[C];
    __shared__ float s_w[C];
    __shared__ float s_part[NWARP * C];
    __shared__ unsigned int s_hash[HSIZE];

    const int bk   = blockIdx.x;   // 0..B*K-1
    const int b    = bk >> 7;      // / K
    const int kk   = bk & (K - 1);
    const int tid  = threadIdx.x;
    const int lane = tid & 31;
    const int wid  = tid >> 5;

    // Stage centers: means, inv-sigma, values
    if (tid < C * 2) {
        int gidx = ((b * K + kk) * C) * 2 + tid;
        float m  = means[gidx];
        float sg = sigmas[gidx];
        s_mean[tid] = m;
        s_inv[tid]  = sqrtf(1.0f / (1e-6f + sg));   // sqrt(1/(EPS+sigma))
    }
    if (tid < C) {
        s_val[tid] = values[(b * K + kk) * C + tid];
    }
    for (int i = tid; i < HSIZE; i += P) s_hash[i] = 0xFFFFFFFFu;
    __syncthreads();

    // ---- Generate this thread's integer tuple (must match JAX f32 exactly) ----
    const int cc = tid / PPC;
    const int j  = tid - cc * PPC;
    const float m0 = s_mean[2 * cc + 0];
    const float m1 = s_mean[2 * cc + 1];
    const float CEPS = (float)(1.0 - 1e-6);  // (1 - EPS) rounded to f32

    int i0, i1;
    if (j < 4) {
        // fm = product([T,F], repeat=2): bit0 True for j in {0,1}, bit1 True for j in {0,2}
        i0 = (int)((j < 2)        ? floorf(m0) : ceilf(m0));
        i1 = (int)(((j & 1) == 0) ? floorf(m1) : ceilf(m1));
    } else if (j < 8) {
        int gi = j - 4;
        int base = (((b * K + kk) * C + cc) * G + gi) * 2;
        float u0 = su[base], u1 = su[base + 1];
        // floor(u * (1-eps) * 1024): two rn-multiplies, no contraction
        i0 = (int)floorf(__fmul_rn(__fmul_rn(u0, CEPS), 1024.0f));
        i1 = (int)floorf(__fmul_rn(__fmul_rn(u1, CEPS), 1024.0f));
    } else {
        int ri = j - 8;
        int base = (((b * K + kk) * C + cc) * RAD + ri) * 2;
        float u0 = ru[base], u1 = ru[base + 1];
        float mn0 = rintf(m0), mn1 = rintf(m1);   // jnp.round = half-to-even
        float l0 = mn0 - 8.0f; if (l0 < 0.0f) l0 = 0.0f; if (mn0 + 8.0f > 1024.0f) l0 = 1008.0f;
        float l1 = mn1 - 8.0f; if (l1 < 0.0f) l1 = 0.0f; if (mn1 + 8.0f > 1024.0f) l1 = 1008.0f;
        // floor(u*(1-eps)*16 + lower): forbid fma contraction of the last mul+add
        i0 = (int)floorf(__fadd_rn(__fmul_rn(__fmul_rn(u0, CEPS), 16.0f), l0));
        i1 = (int)floorf(__fadd_rn(__fmul_rn(__fmul_rn(u1, CEPS), 16.0f), l1));
    }

    // ---- Dedup via concurrent SMEM hash set (duplicates are identical points,
    //      so "keep any one" is numerically identical to the reference's sort) ----
    const unsigned int myid = (unsigned int)(i0 * IN + i1);
    bool dup = false;
    unsigned int h = (myid * 2654435769u) >> 22;  // top 10 bits -> 0..1023
    while (true) {
        unsigned int old = atomicCAS(&s_hash[h], 0xFFFFFFFFu, myid);
        if (old == 0xFFFFFFFFu) break;            // inserted: this thread is the keeper
        if (old == myid) { dup = true; break; }   // already present: duplicate
        h = (h + 1) & (HSIZE - 1);
    }

    // ---- Densities against all 32 centers ----
    const float pf0 = (float)i0, pf1 = (float)i1;
    float dens[C];
#pragma unroll
    for (int c = 0; c < C; c++) {
        float d0 = (pf0 - s_mean[2 * c + 0]) * s_inv[2 * c + 0];
        float d1 = (pf1 - s_mean[2 * c + 1]) * s_inv[2 * c + 1];
        float a = d0 * d0 + d1 * d1;
        dens[c] = dup ? 0.0f : expf(-0.5f * a);
    }

    // ---- Per-center denominators: warp butterfly reduce (lane c keeps sum_c),
    //      then cross-warp reduce in SMEM ----
    float mysum = 0.0f;
#pragma unroll
    for (int c = 0; c < C; c++) {
        float v = dens[c];
        v += __shfl_xor_sync(0xFFFFFFFFu, v, 16);
        v += __shfl_xor_sync(0xFFFFFFFFu, v, 8);
        v += __shfl_xor_sync(0xFFFFFFFFu, v, 4);
        v += __shfl_xor_sync(0xFFFFFFFFu, v, 2);
        v += __shfl_xor_sync(0xFFFFFFFFu, v, 1);
        if (lane == c) mysum = v;
    }
    s_part[wid * C + lane] = mysum;
    __syncthreads();
    if (tid < C) {
        float s = 0.0f;
#pragma unroll
        for (int w = 0; w < NWARP; w++) s += s_part[w * C + tid];
        s_w[tid] = s_val[tid] / s;   // values[c] / denom[c]
    }
    __syncthreads();

    // ---- Mix and scatter ----
    float val = 0.0f;
#pragma unroll
    for (int c = 0; c < C; c++) val += dens[c] * s_w[c];

    if (!dup) {
        float contrib = val * __ldg(&x[b * IN + i1]);
        atomicAdd(&out[b * OUTN + i0], contrib);
    }
}

extern "C" void kernel_launch(void* const* d_in, const int* in_sizes, int n_in,
                              void* d_out, int out_size) {
    const float* x      = (const float*)d_in[0];
    const float* means  = (const float*)d_in[1];
    const float* sigmas = (const float*)d_in[2];
    const float* values = (const float*)d_in[3];
    const float* su     = (const float*)d_in[4];
    const float* ru     = (const float*)d_in[5];
    float* out = (float*)d_out;

    zero_kernel<<<(out_size + 255) / 256, 256>>>(out, out_size);
    sparse_layer_kernel<<<B * K, P>>>(x, means, sigmas, values, su, ru, out);
}

// round 7
// speedup vs baseline: 4.6891x; 4.6891x over previous
#include <cuda_runtime.h>

// Problem constants (from reference setup_inputs)
#define B     8
#define C     32
#define G     4
#define RAD   4
#define K     128         // NTOT / C
#define PPC   12          // points per center: 4 neighbor + 4 sampled + 4 rr
#define P     (C * PPC)   // 384 points per (b,k)
#define IN    1024
#define OUTN  1024
#define HSIZE 1024        // smem hash table slots
#define CH    16          // centers per chunk (2 chunks of 16)
#define NCHUNK 2
#define NSEG  24          // P / 16 column-sum segments

__global__ void zero_kernel(float* __restrict__ out, int n) {
    int i = blockIdx.x * blockDim.x + threadIdx.x;
    if (i < n) out[i] = 0.0f;
}

// exp2(t) for t <= 0, no MUFU: magic-number split t = r + f, f in [-0.5,0.5],
// 2^r built from bits, 2^f via degree-5 Taylor (rel err ~2.4e-6).
__device__ __forceinline__ float exp2_fast(float t) {
    t = fmaxf(t, -126.0f);                       // clamp (also handles dup bias)
    float z = t + 12582912.0f;                   // 1.5*2^23: RN -> round(t) in mantissa
    float f = t - (z - 12582912.0f);             // f in [-0.5, 0.5]
    unsigned int e = ((unsigned int)__float_as_int(z) + 0xB4C0007Fu) << 23; // (r+127)<<23
    float p =              0.0013333558f;
    p = fmaf(p, f,         0.0096181291f);
    p = fmaf(p, f,         0.0555041087f);
    p = fmaf(p, f,         0.2402265069f);
    p = fmaf(p, f,         0.6931471806f);
    p = fmaf(p, f,         1.0f);
    return __int_as_float(e) * p;
}

__global__ __launch_bounds__(P, 4) void sparse_layer_kernel(
    const float* __restrict__ x,       // (B, IN)
    const float* __restrict__ means,   // (B, K, C, 2)
    const float* __restrict__ sigmas,  // (B, K, C, 2)
    const float* __restrict__ values,  // (B, K, C)
    const float* __restrict__ su,      // (B, K, C, G, 2)
    const float* __restrict__ ru,      // (B, K, C, RAD, 2)
    float* __restrict__ out)           // (B, OUTN)
{
    __shared__ float4 s_ctr[C];            // {inv0, inv1, -m0*inv0, -m1*inv1}
    __shared__ float  s_mean[C * 2];       // raw means (bit-exact floor/ceil/rint)
    __shared__ float  s_val[C];
    __shared__ float  s_w[CH];
    __shared__ float  s_part[NSEG * CH];   // 24 x 16 column partials
    __shared__ float  s_dens[P * (CH + 1)];// 384 x 16, stride 17 (conflict-free)
    __shared__ unsigned int s_hash[HSIZE];

    const int bk  = blockIdx.x;
    const int b   = bk >> 7;
    const int kk  = bk & (K - 1);
    const int tid = threadIdx.x;

    // Stage centers
    if (tid < C) {
        const float* mp = means  + (size_t)(((b * K + kk) * C + tid) * 2);
        const float* sp = sigmas + (size_t)(((b * K + kk) * C + tid) * 2);
        float m0 = mp[0], m1 = mp[1];
        float i0v = sqrtf(1.0f / (1e-6f + sp[0]));
        float i1v = sqrtf(1.0f / (1e-6f + sp[1]));
        s_mean[2 * tid]     = m0;
        s_mean[2 * tid + 1] = m1;
        s_ctr[tid] = make_float4(i0v, i1v, -m0 * i0v, -m1 * i1v);
        s_val[tid] = values[(b * K + kk) * C + tid];
    }
    for (int i = tid; i < HSIZE; i += P) s_hash[i] = 0xFFFFFFFFu;
    __syncthreads();

    // ---- Generate this thread's integer tuple (must match JAX f32 exactly) ----
    const int cc = tid / PPC;
    const int j  = tid - cc * PPC;
    const float m0 = s_mean[2 * cc + 0];
    const float m1 = s_mean[2 * cc + 1];
    const float CEPS = (float)(1.0 - 1e-6);

    int i0, i1;
    if (j < 4) {
        i0 = (int)((j < 2)        ? floorf(m0) : ceilf(m0));
        i1 = (int)(((j & 1) == 0) ? floorf(m1) : ceilf(m1));
    } else if (j < 8) {
        int base = (((b * K + kk) * C + cc) * G + (j - 4)) * 2;
        float u0 = su[base], u1 = su[base + 1];
        i0 = (int)floorf(__fmul_rn(__fmul_rn(u0, CEPS), 1024.0f));
        i1 = (int)floorf(__fmul_rn(__fmul_rn(u1, CEPS), 1024.0f));
    } else {
        int base = (((b * K + kk) * C + cc) * RAD + (j - 8)) * 2;
        float u0 = ru[base], u1 = ru[base + 1];
        float mn0 = rintf(m0), mn1 = rintf(m1);     // jnp.round = half-to-even
        float l0 = mn0 - 8.0f; if (l0 < 0.0f) l0 = 0.0f; if (mn0 + 8.0f > 1024.0f) l0 = 1008.0f;
        float l1 = mn1 - 8.0f; if (l1 < 0.0f) l1 = 0.0f; if (mn1 + 8.0f > 1024.0f) l1 = 1008.0f;
        i0 = (int)floorf(__fadd_rn(__fmul_rn(__fmul_rn(u0, CEPS), 16.0f), l0));
        i1 = (int)floorf(__fadd_rn(__fmul_rn(__fmul_rn(u1, CEPS), 16.0f), l1));
    }

    // ---- Dedup via concurrent SMEM hash set (duplicates are identical tuples) ----
    const unsigned int myid = (unsigned int)(i0 * IN + i1);
    bool dup = false;
    unsigned int h = (myid * 2654435769u) >> 22;
    while (true) {
        unsigned int old = atomicCAS(&s_hash[h], 0xFFFFFFFFu, myid);
        if (old == 0xFFFFFFFFu) break;
        if (old == myid) { dup = true; break; }
        h = (h + 1) & (HSIZE - 1);
    }

    // dup rows: bias pf0 huge -> exp arg clamps to -126 -> density ~1.2e-38 (== 0
    // relative to denominators, which are >= ~1e-5 from each center's own neighbors)
    const float pf0 = dup ? 1e30f : (float)i0;
    const float pf1 = (float)i1;

    float val = 0.0f;
#pragma unroll
    for (int ch = 0; ch < NCHUNK; ch++) {
        // Densities for 16 centers -> SMEM matrix (no MUFU)
#pragma unroll
        for (int c = 0; c < CH; c++) {
            float4 q = s_ctr[ch * CH + c];
            float d0 = fmaf(pf0, q.x, q.z);
            float d1 = fmaf(pf1, q.y, q.w);
            float a  = fmaf(d1, d1, d0 * d0);
            s_dens[tid * (CH + 1) + c] = exp2_fast(a * -0.72134752044f); // -0.5*log2(e)
        }
        __syncthreads();

        // Column sums: 24 segments x 16 columns
        {
            int c = tid & (CH - 1);
            int seg = tid >> 4;
            float s = 0.0f;
#pragma unroll
            for (int i = 0; i < 16; i++)
                s += s_dens[(seg * 16 + i) * (CH + 1) + c];
            s_part[seg * CH + c] = s;
        }
        __syncthreads();

        if (tid < CH) {
            float s = 0.0f;
#pragma unroll
            for (int g2 = 0; g2 < NSEG; g2++) s += s_part[g2 * CH + tid];
            s_w[tid] = s_val[ch * CH + tid] / s;      // values[c] / denom[c]
        }
        __syncthreads();

        // Row mix for this chunk
#pragma unroll
        for (int c = 0; c < CH; c++)
            val = fmaf(s_dens[tid * (CH + 1) + c], s_w[c], val);
        __syncthreads();   // all mix reads done before next chunk overwrites
    }

    if (!dup) {
        float contrib = val * __ldg(&x[b * IN + i1]);
        atomicAdd(&out[b * OUTN + i0], contrib);
    }
}

extern "C" void kernel_launch(void* const* d_in, const int* in_sizes, int n_in,
                              void* d_out, int out_size) {
    const float* x      = (const float*)d_in[0];
    const float* means  = (const float*)d_in[1];
    const float* sigmas = (const float*)d_in[2];
    const float* values = (const float*)d_in[3];
    const float* su     = (const float*)d_in[4];
    const float* ru     = (const float*)d_in[5];
    float* out = (float*)d_out;

    zero_kernel<<<(out_size + 255) / 256, 256>>>(out, out_size);
    sparse_layer_kernel<<<B * K, P>>>(x, means, sigmas, values, su, ru, out);
}

// round 8
// speedup vs baseline: 4.7347x; 1.0097x over previous
#include <cuda_runtime.h>

// Problem constants (from reference setup_inputs)
#define B     8
#define C     32
#define G     4
#define RAD   4
#define K     128         // NTOT / C
#define PPC   12          // points per center
#define P     (C * PPC)   // 384 points per (b,k)
#define IN    1024
#define OUTN  1024
#define HSIZE 1024
#define CH    16          // centers per chunk
#define NCHUNK 2
#define DSTR  20          // s_dens row stride in floats (16 + 4 pad, float4-aligned,
                          // 20k mod 32 cycles 8 distinct bank-quads -> conflict-free)
#define TASKS_PER_CTA 2

__global__ void zero_kernel(float4* __restrict__ out, int n4) {
    int i = blockIdx.x * blockDim.x + threadIdx.x;
    if (i < n4) out[i] = make_float4(0.f, 0.f, 0.f, 0.f);
}

// 2^(-a) for a >= 0 (a may be +inf), no MUFU.
// z = RN(M - a) encodes round(-a) in its mantissa; exponent applied via int add.
__device__ __forceinline__ float exp2_neg(float a) {
    a = fminf(a, 126.0f);
    const float M = 12582912.0f;          // 1.5 * 2^23
    float z = M - a;                      // = M + round(-a), exact in mantissa
    float f = (M - z) - a;                // frac in [-0.5, 0.5]
    float p =          0.0013333558f;
    p = fmaf(p, f,     0.0096181291f);
    p = fmaf(p, f,     0.0555041087f);
    p = fmaf(p, f,     0.2402265069f);
    p = fmaf(p, f,     0.6931471806f);
    p = fmaf(p, f,     1.0f);
    // bits(p) + (r << 23): (0x4B400000 << 23) wraps to 0, so bits(z)<<23 == r<<23 mod 2^32
    return __int_as_float(__float_as_int(p) + (__float_as_int(z) << 23));
}

__global__ __launch_bounds__(P, 4) void sparse_layer_kernel(
    const float* __restrict__ x,       // (B, IN)
    const float* __restrict__ means,   // (B, K, C, 2)
    const float* __restrict__ sigmas,  // (B, K, C, 2)
    const float* __restrict__ values,  // (B, K, C)
    const float* __restrict__ su,      // (B, K, C, G, 2)
    const float* __restrict__ ru,      // (B, K, C, RAD, 2)
    float* __restrict__ out)           // (B, OUTN)
{
    __shared__ float4 s_ctr[C];             // {inv0*s, inv1*s, -m0*inv0*s, -m1*inv1*s}, s=sqrt(0.5*log2 e)
    __shared__ float  s_mean[C * 2];        // raw means (bit-exact floor/ceil/rint)
    __shared__ float  s_val[C];
    __shared__ float4 s_w4[CH / 4];
    __shared__ float  s_part[48 * DSTR];    // level-1 column partials (padded)
    __shared__ float  s_dens[P * DSTR];     // 384 x 16 densities, stride 20
    __shared__ unsigned int s_hash[HSIZE];

    const int tid = threadIdx.x;
    const float CEPS = (float)(1.0 - 1e-6);

#pragma unroll 1
    for (int t2 = 0; t2 < TASKS_PER_CTA; t2++) {
        const int task = blockIdx.x * TASKS_PER_CTA + t2;   // = b*K + kk
        const int b = task >> 7;

        // ---- Stage centers ----
        if (tid < C) {
            float2 m2 = ((const float2*)means )[task * C + tid];
            float2 g2 = ((const float2*)sigmas)[task * C + tid];
            float sc = sqrtf(0.72134752f);                   // sqrt(0.5*log2(e))
            float i0v = sqrtf(1.0f / (1e-6f + g2.x)) * sc;
            float i1v = sqrtf(1.0f / (1e-6f + g2.y)) * sc;
            s_mean[2 * tid]     = m2.x;
            s_mean[2 * tid + 1] = m2.y;
            s_ctr[tid] = make_float4(i0v, i1v, -m2.x * i0v, -m2.y * i1v);
            s_val[tid] = values[task * C + tid];
        }
        for (int i = tid; i < HSIZE; i += P) s_hash[i] = 0xFFFFFFFFu;
        __syncthreads();

        // ---- Generate integer tuple (bit-exact vs JAX f32) ----
        const int cc = tid / PPC;
        const int j  = tid - cc * PPC;
        const float m0 = s_mean[2 * cc + 0];
        const float m1 = s_mean[2 * cc + 1];

        int i0, i1;
        if (j < 4) {
            i0 = (int)((j < 2)        ? floorf(m0) : ceilf(m0));
            i1 = (int)(((j & 1) == 0) ? floorf(m1) : ceilf(m1));
        } else if (j < 8) {
            float2 u = ((const float2*)su)[(task * C + cc) * G + (j - 4)];
            i0 = (int)floorf(__fmul_rn(__fmul_rn(u.x, CEPS), 1024.0f));
            i1 = (int)floorf(__fmul_rn(__fmul_rn(u.y, CEPS), 1024.0f));
        } else {
            float2 u = ((const float2*)ru)[(task * C + cc) * RAD + (j - 8)];
            float mn0 = rintf(m0), mn1 = rintf(m1);          // half-to-even
            float l0 = mn0 - 8.0f; if (l0 < 0.0f) l0 = 0.0f; if (mn0 + 8.0f > 1024.0f) l0 = 1008.0f;
            float l1 = mn1 - 8.0f; if (l1 < 0.0f) l1 = 0.0f; if (mn1 + 8.0f > 1024.0f) l1 = 1008.0f;
            i0 = (int)floorf(__fadd_rn(__fmul_rn(__fmul_rn(u.x, CEPS), 16.0f), l0));
            i1 = (int)floorf(__fadd_rn(__fmul_rn(__fmul_rn(u.y, CEPS), 16.0f), l1));
        }

        // ---- Dedup: concurrent SMEM hash set (dups are identical tuples) ----
        const unsigned int myid = (unsigned int)(i0 * IN + i1);
        bool dup = false;
        unsigned int h = (myid * 2654435769u) >> 22;
        while (true) {
            unsigned int old = atomicCAS(&s_hash[h], 0xFFFFFFFFu, myid);
            if (old == 0xFFFFFFFFu) break;
            if (old == myid) { dup = true; break; }
            h = (h + 1) & (HSIZE - 1);
        }

        // dup rows -> pf0 huge -> a = inf -> clamped -> density ~1e-38 (== 0 vs denoms)
        const float pf0 = dup ? 1e30f : (float)i0;
        const float pf1 = (float)i1;

        float val = 0.0f;
#pragma unroll
        for (int ch = 0; ch < NCHUNK; ch++) {
            // Densities for 16 centers, written as 4x STS.128
#pragma unroll
            for (int g = 0; g < 4; g++) {
                float r[4];
#pragma unroll
                for (int q = 0; q < 4; q++) {
                    float4 ct = s_ctr[ch * CH + g * 4 + q];
                    float d0 = fmaf(pf0, ct.x, ct.z);
                    float d1 = fmaf(pf1, ct.y, ct.w);
                    float a  = fmaf(d1, d1, d0 * d0);        // already scaled by 0.5*log2e
                    r[q] = exp2_neg(a);
                }
                *(float4*)&s_dens[tid * DSTR + g * 4] = make_float4(r[0], r[1], r[2], r[3]);
            }
            __syncthreads();

            // Column sums level 1: 192 threads, each: float4 of 4 cols over 8 rows
            if (tid < 192) {
                int g = tid / 48, i = tid % 48;
                float4 acc = make_float4(0.f, 0.f, 0.f, 0.f);
#pragma unroll
                for (int r = 0; r < 8; r++) {
                    float4 d = *(const float4*)&s_dens[(i + 48 * r) * DSTR + g * 4];
                    acc.x += d.x; acc.y += d.y; acc.z += d.z; acc.w += d.w;
                }
                *(float4*)&s_part[i * DSTR + g * 4] = acc;   // s_part[i*20 + c]
            }
            __syncthreads();

            // Level 2 + weights: 16 threads
            if (tid < CH) {
                float a0 = 0.f, a1 = 0.f, a2 = 0.f, a3 = 0.f;
#pragma unroll
                for (int i = 0; i < 48; i += 4) {
                    a0 += s_part[(i + 0) * DSTR + tid];
                    a1 += s_part[(i + 1) * DSTR + tid];
                    a2 += s_part[(i + 2) * DSTR + tid];
                    a3 += s_part[(i + 3) * DSTR + tid];
                }
                ((float*)s_w4)[tid] = s_val[ch * CH + tid] / ((a0 + a1) + (a2 + a3));
            }
            __syncthreads();

            // Row mix: 4x LDS.128
#pragma unroll
            for (int g = 0; g < 4; g++) {
                float4 d = *(const float4*)&s_dens[tid * DSTR + g * 4];
                float4 w = s_w4[g];
                val = fmaf(d.x, w.x, val);
                val = fmaf(d.y, w.y, val);
                val = fmaf(d.z, w.z, val);
                val = fmaf(d.w, w.w, val);
            }
            __syncthreads();   // protect s_dens/s_w4 before next chunk/task
        }

        if (!dup) {
            float contrib = val * __ldg(&x[b * IN + i1]);
            atomicAdd(&out[b * OUTN + i0], contrib);
        }
    }
}

extern "C" void kernel_launch(void* const* d_in, const int* in_sizes, int n_in,
                              void* d_out, int out_size) {
    const float* x      = (const float*)d_in[0];
    const float* means  = (const float*)d_in[1];
    const float* sigmas = (const float*)d_in[2];
    const float* values = (const float*)d_in[3];
    const float* su     = (const float*)d_in[4];
    const float* ru     = (const float*)d_in[5];
    float* out = (float*)d_out;

    int n4 = out_size / 4;
    zero_kernel<<<(n4 + 255) / 256, 256>>>((float4*)out, n4);
    sparse_layer_kernel<<<(B * K) / TASKS_PER_CTA, P>>>(x, means, sigmas, values, su, ru, out);
}

// round 12
// speedup vs baseline: 4.8631x; 1.0271x over previous
#include <cuda_runtime.h>

// Problem constants (from reference setup_inputs)
#define B     8
#define C     32
#define G     4
#define RAD   4
#define K     128         // NTOT / C
#define PPC   12          // points per center
#define P     (C * PPC)   // 384 points per (b,k)
#define IN    1024
#define OUTN  1024
#define HSIZE 1024
#define CH    16          // centers per chunk
#define NCHUNK 2
#define DSTR  20          // s_dens row stride in floats (16 + 4 pad, float4-aligned)
#define TASKS_PER_CTA 2

typedef unsigned long long ull;

__global__ void zero_kernel(float4* __restrict__ out, int n4) {
    int i = blockIdx.x * blockDim.x + threadIdx.x;
    if (i < n4) out[i] = make_float4(0.f, 0.f, 0.f, 0.f);
}

// ---- packed f32x2 helpers (Blackwell FFMA2 path; ptxas never auto-fuses) ----
__device__ __forceinline__ ull pk2(float lo, float hi) {
    ull r; asm("mov.b64 %0,{%1,%2};" : "=l"(r) : "f"(lo), "f"(hi)); return r;
}
__device__ __forceinline__ void upk2(ull v, float& lo, float& hi) {
    asm("mov.b64 {%0,%1},%2;" : "=f"(lo), "=f"(hi) : "l"(v));
}
__device__ __forceinline__ ull fma2(ull a, ull b, ull c) {
    ull d; asm("fma.rn.f32x2 %0,%1,%2,%3;" : "=l"(d) : "l"(a), "l"(b), "l"(c)); return d;
}
__device__ __forceinline__ ull mul2(ull a, ull b) {
    ull d; asm("mul.rn.f32x2 %0,%1,%2;" : "=l"(d) : "l"(a), "l"(b)); return d;
}
__device__ __forceinline__ ull add2(ull a, ull b) {
    ull d; asm("add.rn.f32x2 %0,%1,%2;" : "=l"(d) : "l"(a), "l"(b)); return d;
}

// 2^(-a) for packed pair a >= 0 (components may be inf), no MUFU.
__device__ __forceinline__ void exp2_neg2(ull ap, float& r0, float& r1) {
    float a0, a1; upk2(ap, a0, a1);
    a0 = fminf(a0, 126.0f); a1 = fminf(a1, 126.0f);
    ap = pk2(a0, a1);
    const ull Mp = pk2(12582912.0f, 12582912.0f);   // 1.5*2^23
    const ull N1 = pk2(-1.0f, -1.0f);
    ull z  = fma2(ap, N1, Mp);     // M - a  (mantissa encodes -round(a))
    ull ra = fma2(z,  N1, Mp);     // round(a)
    ull f  = fma2(ap, N1, ra);     // round(a) - a  in [-0.5, 0.5]
    ull p  = pk2(0.0013333558f, 0.0013333558f);
    p = fma2(p, f, pk2(0.0096181291f, 0.0096181291f));
    p = fma2(p, f, pk2(0.0555041087f, 0.0555041087f));
    p = fma2(p, f, pk2(0.2402265069f, 0.2402265069f));
    p = fma2(p, f, pk2(0.6931471806f, 0.6931471806f));
    p = fma2(p, f, pk2(1.0f, 1.0f));
    float p0, p1, z0, z1; upk2(p, p0, p1); upk2(z, z0, z1);
    // bits(p) + (bits(z)<<23): (0x4B400000<<23) wraps to 0, so this adds -round(a) to the exponent
    r0 = __int_as_float(__float_as_int(p0) + (__float_as_int(z0) << 23));
    r1 = __int_as_float(__float_as_int(p1) + (__float_as_int(z1) << 23));
}

__global__ __launch_bounds__(P, 4) void sparse_layer_kernel(
    const float* __restrict__ x,       // (B, IN)
    const float* __restrict__ means,   // (B, K, C, 2)
    const float* __restrict__ sigmas,  // (B, K, C, 2)
    const float* __restrict__ values,  // (B, K, C)
    const float* __restrict__ su,      // (B, K, C, G, 2)
    const float* __restrict__ ru,      // (B, K, C, RAD, 2)
    float* __restrict__ out)           // (B, OUTN)
{
    // Center constants pre-packed per center-PAIR p:
    //   s_pk[2p]   = { (inv0a,inv0b), (inv1a,inv1b) }   (scaled by sqrt(0.5*log2 e))
    //   s_pk[2p+1] = { (off0a,off0b), (off1a,off1b) }   off = -m*inv
    __shared__ ulonglong2 s_pk[C];
    __shared__ float  s_mean[C * 2];        // raw means (bit-exact floor/ceil/rint)
    __shared__ float  s_val[C];
    __shared__ __align__(16) float s_w[CH];
    __shared__ __align__(16) float s_part[48 * DSTR];
    __shared__ __align__(16) float s_dens[P * DSTR];   // 384 x 16, stride 20
    __shared__ unsigned int s_hash[HSIZE];

    const int tid = threadIdx.x;
    const float CEPS = (float)(1.0 - 1e-6);

#pragma unroll 1
    for (int t2 = 0; t2 < TASKS_PER_CTA; t2++) {
        const int task = blockIdx.x * TASKS_PER_CTA + t2;   // = b*K + kk
        const int b = task >> 7;

        // ---- Stage centers directly into packed-pair layout ----
        if (tid < C) {
            float2 m2 = ((const float2*)means )[task * C + tid];
            float2 g2 = ((const float2*)sigmas)[task * C + tid];
            float sc  = sqrtf(0.72134752f);                 // sqrt(0.5*log2 e)
            float i0v = sqrtf(1.0f / (1e-6f + g2.x)) * sc;
            float i1v = sqrtf(1.0f / (1e-6f + g2.y)) * sc;
            float* f = (float*)s_pk;
            int p = tid >> 1, l = tid & 1;
            f[p * 8 + 0 + l] = i0v;
            f[p * 8 + 2 + l] = i1v;
            f[p * 8 + 4 + l] = -m2.x * i0v;
            f[p * 8 + 6 + l] = -m2.y * i1v;
            s_mean[2 * tid]     = m2.x;
            s_mean[2 * tid + 1] = m2.y;
            s_val[tid] = values[task * C + tid];
        }
        if (tid < 256) ((uint4*)s_hash)[tid] = make_uint4(~0u, ~0u, ~0u, ~0u);
        __syncthreads();

        // ---- Generate integer tuple (bit-exact vs JAX f32) ----
        const int cc = tid / PPC;
        const int j  = tid - cc * PPC;
        const float m0 = s_mean[2 * cc + 0];
        const float m1 = s_mean[2 * cc + 1];

        int i0, i1;
        if (j < 4) {
            i0 = (int)((j < 2)        ? floorf(m0) : ceilf(m0));
            i1 = (int)(((j & 1) == 0) ? floorf(m1) : ceilf(m1));
        } else if (j < 8) {
            float2 u = ((const float2*)su)[(task * C + cc) * G + (j - 4)];
            i0 = (int)floorf(__fmul_rn(__fmul_rn(u.x, CEPS), 1024.0f));
            i1 = (int)floorf(__fmul_rn(__fmul_rn(u.y, CEPS), 1024.0f));
        } else {
            float2 u = ((const float2*)ru)[(task * C + cc) * RAD + (j - 8)];
            float mn0 = rintf(m0), mn1 = rintf(m1);          // half-to-even
            float l0 = mn0 - 8.0f; if (l0 < 0.0f) l0 = 0.0f; if (mn0 + 8.0f > 1024.0f) l0 = 1008.0f;
            float l1 = mn1 - 8.0f; if (l1 < 0.0f) l1 = 0.0f; if (mn1 + 8.0f > 1024.0f) l1 = 1008.0f;
            i0 = (int)floorf(__fadd_rn(__fmul_rn(__fmul_rn(u.x, CEPS), 16.0f), l0));
            i1 = (int)floorf(__fadd_rn(__fmul_rn(__fmul_rn(u.y, CEPS), 16.0f), l1));
        }

        // ---- Dedup: concurrent SMEM hash set (dups are identical tuples) ----
        const unsigned int myid = (unsigned int)(i0 * IN + i1);
        bool dup = false;
        unsigned int h = (myid * 2654435769u) >> 22;
        while (true) {
            unsigned int old = atomicCAS(&s_hash[h], 0xFFFFFFFFu, myid);
            if (old == 0xFFFFFFFFu) break;
            if (old == myid) { dup = true; break; }
            h = (h + 1) & (HSIZE - 1);
        }

        // dup rows -> pf0 huge -> a = inf -> clamped to 126 -> density ~1e-38 (== 0 vs denoms)
        const float pf0 = dup ? 1e30f : (float)i0;
        const float pf1 = (float)i1;
        const ull pf0p = pk2(pf0, pf0);
        const ull pf1p = pk2(pf1, pf1);

        ull vp = 0;   // packed mix accumulator across both chunks
#pragma unroll
        for (int ch = 0; ch < NCHUNK; ch++) {
            // Densities: 8 center-pairs via packed f32x2, written as 4x STS.128
#pragma unroll
            for (int g = 0; g < 4; g++) {
                float r[4];
#pragma unroll
                for (int q = 0; q < 2; q++) {
                    int p = ch * 8 + 2 * g + q;
                    ulonglong2 qi = s_pk[2 * p];
                    ulonglong2 qo = s_pk[2 * p + 1];
                    ull d0 = fma2(pf0p, qi.x, qo.x);
                    ull d1 = fma2(pf1p, qi.y, qo.y);
                    ull a  = fma2(d0, d0, mul2(d1, d1));     // pre-scaled by 0.5*log2 e
                    exp2_neg2(a, r[2 * q], r[2 * q + 1]);
                }
                *(float4*)&s_dens[tid * DSTR + g * 4] = make_float4(r[0], r[1], r[2], r[3]);
            }
            __syncthreads();

            // Column sums level 1: 192 threads, packed adds over 8 rows
            if (tid < 192) {
                int g = tid / 48, i = tid % 48;
                ull a0 = 0, a1 = 0;
#pragma unroll
                for (int r = 0; r < 8; r++) {
                    ulonglong2 d = *(const ulonglong2*)&s_dens[(i + 48 * r) * DSTR + g * 4];
                    a0 = add2(a0, d.x);
                    a1 = add2(a1, d.y);
                }
                ulonglong2 o; o.x = a0; o.y = a1;
                *(ulonglong2*)&s_part[i * DSTR + g * 4] = o;
            }
            __syncthreads();

            // Level 2: one warp, 24-row chains + shfl combine, then 16 divides
            if (tid < 32) {
                int col = tid & 15, hf = tid >> 4;
                float s = 0.0f;
#pragma unroll
                for (int k = 0; k < 24; k++)
                    s += s_part[(hf * 24 + k) * DSTR + col];
                s += __shfl_xor_sync(0xFFFFFFFFu, s, 16);
                if (tid < CH)
                    s_w[tid] = s_val[ch * CH + tid] / s;     // values[c] / denom[c]
            }
            __syncthreads();

            // Row mix: packed FMAs
#pragma unroll
            for (int g = 0; g < 4; g++) {
                ulonglong2 d = *(const ulonglong2*)&s_dens[tid * DSTR + g * 4];
                ulonglong2 w = ((const ulonglong2*)s_w)[g];
                vp = fma2(d.x, w.x, vp);
                vp = fma2(d.y, w.y, vp);
            }
            __syncthreads();   // protect s_dens/s_w before next chunk/task
        }

        if (!dup) {
            float v0, v1; upk2(vp, v0, v1);
            float contrib = (v0 + v1) * __ldg(&x[b * IN + i1]);
            atomicAdd(&out[b * OUTN + i0], contrib);
        }
    }
}

extern "C" void kernel_launch(void* const* d_in, const int* in_sizes, int n_in,
                              void* d_out, int out_size) {
    const float* x      = (const float*)d_in[0];
    const float* means  = (const float*)d_in[1];
    const float* sigmas = (const float*)d_in[2];
    const float* values = (const float*)d_in[3];
    const float* su     = (const float*)d_in[4];
    const float* ru     = (const float*)d_in[5];
    float* out = (float*)d_out;

    int n4 = out_size / 4;
    zero_kernel<<<(n4 + 255) / 256, 256>>>((float4*)out, n4);
    sparse_layer_kernel<<<(B * K) / TASKS_PER_CTA, P>>>(x, means, sigmas, values, su, ru, out);
}